// round 2
// baseline (speedup 1.0000x reference)
#include <cuda_runtime.h>
#include <cuda_bf16.h>

// Problem constants
#define BB   64          // batch
#define NN   200         // frames
#define PP   80          // frame period (chunk length)
#define MM   30          // filter order
#define TT   (NN * PP)   // 16000 samples
#define NA   31          // coeffs per frame (K + 30 taps)

// Scratch: state-transition matrices M[b][c][col q][row r], driven-run end states V,
// and scanned initial states H. Static __device__ arrays (no runtime allocation).
__device__ float g_M[(size_t)BB * NN * MM * MM];   // ~46 MB (L2-resident between phases)
__device__ float g_V[(size_t)BB * NN * MM];
__device__ float g_H[(size_t)BB * NN * MM];

// ---------------------------------------------------------------------------
// Phase 1: per (b, chunk c) compute M_c (30 homogeneous unit-response columns)
// and v_c (zero-init driven run). One warp per chunk; lane i = column i
// (i<30), lane 30 = driven run, lane 31 helps fill smem then idles in compute.
// Interpolated coefficients for all 80 steps precomputed into SMEM:
//   cs[t][0..29] = interpolated a_1..a_30, cs[t][30] = K_t, cs[t][31] = x_t.
// ---------------------------------------------------------------------------
__global__ __launch_bounds__(32) void k_phase1(const float* __restrict__ x,
                                               const float* __restrict__ a)
{
    const int c = blockIdx.x;
    const int b = blockIdx.y;
    const int lane = threadIdx.x;
    const int cn = (c < NN - 1) ? (c + 1) : c;   // a_pad duplicates last frame

    __shared__ float cs[PP][32];

    // Fill coefficient columns (lane = one coefficient slot, loops over t)
    if (lane < 31) {
        const int m_src = (lane < 30) ? (lane + 1) : 0;   // slot<30 -> tap, slot30 -> K
        const int slot  = (lane < 30) ? lane : 30;
        const float base = a[((size_t)b * NN + c)  * NA + m_src];
        const float nxtv = a[((size_t)b * NN + cn) * NA + m_src];
        const float dd = (nxtv - base) * (1.0f / (float)PP);
        #pragma unroll 8
        for (int t = 0; t < PP; ++t)
            cs[t][slot] = fmaf((float)t, dd, base);
    }
    // Fill x into slot 31
    for (int t = lane; t < PP; t += 32)
        cs[t][31] = x[(size_t)b * TT + c * PP + t];
    __syncwarp();

    // History registers: hist[m] = y_{t-1-m}. Unit init for columns, zero for driven.
    float h[MM];
    #pragma unroll
    for (int j = 0; j < MM; ++j)
        h[j] = (j == lane) ? 1.0f : 0.0f;      // lanes >=30: all zero
    const float gsel = (lane == 30) ? 1.0f : 0.0f;

    #pragma unroll
    for (int t = 0; t < PP; ++t) {
        // 8x LDS.128: 30 taps + K + x (warp-wide broadcast, conflict-free)
        float rc[32];
        const float4* row4 = reinterpret_cast<const float4*>(cs[t]);
        #pragma unroll
        for (int u = 0; u < 8; ++u)
            reinterpret_cast<float4*>(rc)[u] = row4[u];

        float s0 = 0.f, s1 = 0.f, s2 = 0.f, s3 = 0.f, s4 = 0.f;
        #pragma unroll
        for (int m = 0; m < MM; m += 5) {
            s0 = fmaf(rc[m + 0], h[m + 0], s0);
            s1 = fmaf(rc[m + 1], h[m + 1], s1);
            s2 = fmaf(rc[m + 2], h[m + 2], s2);
            s3 = fmaf(rc[m + 3], h[m + 3], s3);
            s4 = fmaf(rc[m + 4], h[m + 4], s4);
        }
        const float acc = (s0 + s1) + ((s2 + s3) + s4);
        // lanes 0..29: y = -acc ; lane 30: y = K_t * x_t - acc
        const float y = fmaf(gsel * rc[31], rc[30], -acc);

        #pragma unroll
        for (int j = MM - 1; j > 0; --j) h[j] = h[j - 1];
        h[0] = y;
    }

    const size_t bc = (size_t)b * NN + c;
    if (lane < MM) {
        // Column i of M: M[r][i] = h[r]. Layout g_M[bc][q=i][r] (r contiguous).
        float* dst = &g_M[(bc * MM + lane) * MM];
        #pragma unroll
        for (int r = 0; r < MM; ++r) dst[r] = h[r];
    } else if (lane == MM) {
        float* dst = &g_V[bc * MM];
        #pragma unroll
        for (int r = 0; r < MM; ++r) dst[r] = h[r];
    }
}

// ---------------------------------------------------------------------------
// Phase 2: sequential scan over 200 chunks per batch row.
//   h_{c+1} = M_c h_c + v_c ;  stores H[b][c] = pre-chunk state.
// One warp per batch row. Lane r owns state component r; h broadcast via shfl.
// M rows software-prefetched one chunk ahead (L2-resident).
// ---------------------------------------------------------------------------
__global__ __launch_bounds__(32) void k_phase2()
{
    const int b = blockIdx.x;
    const int lane = threadIdx.x;
    const int rl = (lane < MM) ? lane : (MM - 1);   // clamp to stay in-bounds

    float h = 0.0f;
    float cur[MM], nxt[MM];

    {
        const float* Mp = &g_M[((size_t)b * NN * MM) * MM];
        #pragma unroll
        for (int q = 0; q < MM; ++q) cur[q] = Mp[q * MM + rl];
    }

    for (int c = 0; c < NN; ++c) {
        const size_t bc = (size_t)b * NN + c;
        if (lane < MM) g_H[bc * MM + lane] = h;

        // Prefetch next chunk's M rows before the dependent compute
        if (c + 1 < NN) {
            const float* Mn = &g_M[((bc + 1) * MM) * MM];
            #pragma unroll
            for (int q = 0; q < MM; ++q) nxt[q] = Mn[q * MM + rl];
        }

        float s0 = g_V[bc * MM + rl], s1 = 0.f, s2 = 0.f;
        #pragma unroll
        for (int q = 0; q < MM; q += 3) {
            s0 = fmaf(cur[q + 0], __shfl_sync(0xffffffffu, h, q + 0), s0);
            s1 = fmaf(cur[q + 1], __shfl_sync(0xffffffffu, h, q + 1), s1);
            s2 = fmaf(cur[q + 2], __shfl_sync(0xffffffffu, h, q + 2), s2);
        }
        h = s0 + (s1 + s2);

        #pragma unroll
        for (int q = 0; q < MM; ++q) cur[q] = nxt[q];
    }
}

// ---------------------------------------------------------------------------
// Phase 3: rerun each chunk with the correct initial state, writing outputs.
// One thread per (b, c). Coefficients interpolated in registers (fma from
// base+delta each step, no drift). Fully unrolled so the history shift is
// register renaming. float4 x loads / y stores.
// ---------------------------------------------------------------------------
__global__ __launch_bounds__(128) void k_phase3(const float* __restrict__ x,
                                                const float* __restrict__ a,
                                                float* __restrict__ out)
{
    const int idx = blockIdx.x * blockDim.x + threadIdx.x;
    if (idx >= BB * NN) return;
    const int b = idx / NN;
    const int c = idx % NN;
    const int cn = (c < NN - 1) ? (c + 1) : c;

    float a0[NA], dd[NA];
    #pragma unroll
    for (int m = 0; m < NA; ++m) {
        const float v0 = a[((size_t)b * NN + c)  * NA + m];
        const float v1 = a[((size_t)b * NN + cn) * NA + m];
        a0[m] = v0;
        dd[m] = (v1 - v0) * (1.0f / (float)PP);
    }

    float h[MM];
    {
        const float* Hp = &g_H[((size_t)b * NN + c) * MM];
        #pragma unroll
        for (int r = 0; r < MM; ++r) h[r] = Hp[r];
    }

    const float4* xp = reinterpret_cast<const float4*>(x + (size_t)b * TT + c * PP);
    float4*       op = reinterpret_cast<float4*>(out + (size_t)b * TT + c * PP);

    #pragma unroll
    for (int u = 0; u < PP / 4; ++u) {
        const float4 xq = xp[u];
        const float xv[4] = { xq.x, xq.y, xq.z, xq.w };
        float yv[4];
        #pragma unroll
        for (int j = 0; j < 4; ++j) {
            const float ft = (float)(u * 4 + j);
            float s0 = 0.f, s1 = 0.f, s2 = 0.f, s3 = 0.f, s4 = 0.f;
            #pragma unroll
            for (int m = 0; m < MM; m += 5) {
                s0 = fmaf(fmaf(ft, dd[m + 1], a0[m + 1]), h[m + 0], s0);
                s1 = fmaf(fmaf(ft, dd[m + 2], a0[m + 2]), h[m + 1], s1);
                s2 = fmaf(fmaf(ft, dd[m + 3], a0[m + 3]), h[m + 2], s2);
                s3 = fmaf(fmaf(ft, dd[m + 4], a0[m + 4]), h[m + 3], s3);
                s4 = fmaf(fmaf(ft, dd[m + 5], a0[m + 5]), h[m + 4], s4);
            }
            const float acc = (s0 + s1) + ((s2 + s3) + s4);
            const float cK = fmaf(ft, dd[0], a0[0]);
            const float y = fmaf(cK, xv[j], -acc);
            #pragma unroll
            for (int m = MM - 1; m > 0; --m) h[m] = h[m - 1];
            h[0] = y;
            yv[j] = y;
        }
        float4 yq;
        yq.x = yv[0]; yq.y = yv[1]; yq.z = yv[2]; yq.w = yv[3];
        op[u] = yq;
    }
}

extern "C" void kernel_launch(void* const* d_in, const int* in_sizes, int n_in,
                              void* d_out, int out_size)
{
    // Identify inputs by element count (x: B*T = 1,024,000 ; a: B*N*31 = 396,800)
    const float* x;
    const float* a;
    if (in_sizes[0] == BB * TT) {
        x = (const float*)d_in[0];
        a = (const float*)d_in[1];
    } else {
        x = (const float*)d_in[1];
        a = (const float*)d_in[0];
    }
    float* out = (float*)d_out;

    dim3 g1(NN, BB);
    k_phase1<<<g1, 32>>>(x, a);
    k_phase2<<<BB, 32>>>();
    const int total = BB * NN;
    k_phase3<<<(total + 127) / 128, 128>>>(x, a, out);
}

// round 4
// speedup vs baseline: 1.2413x; 1.2413x over previous
#include <cuda_runtime.h>
#include <cuda_bf16.h>

// Problem constants
#define BB   64          // batch
#define NN   200         // frames
#define PP   80          // frame period (chunk length)
#define MM   30          // filter order
#define MMP  32          // padded row length for M rows (16B-aligned LDG.128)
#define TT   (NN * PP)   // 16000 samples
#define NA   31          // coeffs per frame (K + 30 taps)
#define HALF 40          // phase-1 smem coefficient buffer depth

// Scratch (static __device__, no runtime allocation):
// g_M[bc][r][q] with q padded to 32: M[r][q] = d h_end[r] / d h_start[q]
__device__ float g_M[(size_t)BB * NN * MM * MMP];
__device__ float g_V[(size_t)BB * NN * MM];
__device__ float g_H[(size_t)BB * NN * MM];

// ---------------------------------------------------------------------------
// Phase 1: per (b, chunk c) compute the 30 homogeneous unit-response columns
// (lanes 0..29) and the zero-init driven run (lane 30). One warp per chunk.
// Interpolated coefficients staged in SMEM in two 40-step halves to keep the
// block at 5.25KB smem / <=64 regs so 32 blocks fit per SM.
//   cs[t][0..29] = a_1..a_30 at step t, cs[t][30] = K_t, cs[t][31] = x_t.
// ---------------------------------------------------------------------------
__global__ __launch_bounds__(32, 32) void k_phase1(const float* __restrict__ x,
                                                   const float* __restrict__ a)
{
    const int c = blockIdx.x;
    const int b = blockIdx.y;
    const int lane = threadIdx.x;
    const int cn = (c < NN - 1) ? (c + 1) : c;   // a_pad duplicates last frame

    __shared__ float cs[HALF][32];

    // Per-lane interp params (lane < 31 owns one coefficient slot)
    float base = 0.f, dd = 0.f;
    int slot = 31;
    if (lane < 31) {
        const int m_src = (lane < 30) ? (lane + 1) : 0;   // taps 1..30, lane30 -> K
        slot = (lane < 30) ? lane : 30;
        base = a[((size_t)b * NN + c)  * NA + m_src];
        const float nxtv = a[((size_t)b * NN + cn) * NA + m_src];
        dd = (nxtv - base) * (1.0f / (float)PP);
    }
    const float* xb = x + (size_t)b * TT + c * PP;

    // History regs: h[m] = y_{t-1-m}. Unit init per column, zero for driven run.
    float h[MM];
    #pragma unroll
    for (int j = 0; j < MM; ++j)
        h[j] = (j == lane) ? 1.0f : 0.0f;
    const float gsel = (lane == 30) ? 1.0f : 0.0f;

    #pragma unroll
    for (int half = 0; half < 2; ++half) {
        const int t0 = half * HALF;
        // Fill this half's coefficients + x
        __syncwarp();
        if (lane < 31) {
            #pragma unroll 8
            for (int t = 0; t < HALF; ++t)
                cs[t][slot] = fmaf((float)(t0 + t), dd, base);
        }
        #pragma unroll
        for (int t = lane; t < HALF; t += 32)
            cs[t][31] = xb[t0 + t];
        __syncwarp();

        #pragma unroll
        for (int t = 0; t < HALF; ++t) {
            const float4* row4 = reinterpret_cast<const float4*>(cs[t]);
            float s0 = 0.f, s1 = 0.f, s2 = 0.f, s3 = 0.f;
            // taps 0..15
            {
                const float4 q0 = row4[0], q1 = row4[1], q2 = row4[2], q3 = row4[3];
                s0 = fmaf(q0.x, h[0],  s0); s1 = fmaf(q0.y, h[1],  s1);
                s2 = fmaf(q0.z, h[2],  s2); s3 = fmaf(q0.w, h[3],  s3);
                s0 = fmaf(q1.x, h[4],  s0); s1 = fmaf(q1.y, h[5],  s1);
                s2 = fmaf(q1.z, h[6],  s2); s3 = fmaf(q1.w, h[7],  s3);
                s0 = fmaf(q2.x, h[8],  s0); s1 = fmaf(q2.y, h[9],  s1);
                s2 = fmaf(q2.z, h[10], s2); s3 = fmaf(q2.w, h[11], s3);
                s0 = fmaf(q3.x, h[12], s0); s1 = fmaf(q3.y, h[13], s1);
                s2 = fmaf(q3.z, h[14], s2); s3 = fmaf(q3.w, h[15], s3);
            }
            // taps 16..29 + K (q7.z) + x (q7.w)
            float y;
            {
                const float4 q4 = row4[4], q5 = row4[5], q6 = row4[6], q7 = row4[7];
                s0 = fmaf(q4.x, h[16], s0); s1 = fmaf(q4.y, h[17], s1);
                s2 = fmaf(q4.z, h[18], s2); s3 = fmaf(q4.w, h[19], s3);
                s0 = fmaf(q5.x, h[20], s0); s1 = fmaf(q5.y, h[21], s1);
                s2 = fmaf(q5.z, h[22], s2); s3 = fmaf(q5.w, h[23], s3);
                s0 = fmaf(q6.x, h[24], s0); s1 = fmaf(q6.y, h[25], s1);
                s2 = fmaf(q6.z, h[26], s2); s3 = fmaf(q6.w, h[27], s3);
                s0 = fmaf(q7.x, h[28], s0); s1 = fmaf(q7.y, h[29], s1);
                const float acc = (s0 + s1) + (s2 + s3);
                y = fmaf(gsel * q7.w, q7.z, -acc);   // lane30 adds K_t*x_t
            }
            #pragma unroll
            for (int j = MM - 1; j > 0; --j) h[j] = h[j - 1];
            h[0] = y;
        }
    }

    const size_t bc = (size_t)b * NN + c;
    if (lane < MM) {
        // g_M[bc][r][lane] : lanes write coalesced 30-float rows
        float* dst = &g_M[bc * (MM * MMP)];
        #pragma unroll
        for (int r = 0; r < MM; ++r) dst[r * MMP + lane] = h[r];
    } else if (lane == MM) {
        float* dst = &g_V[bc * MM];
        #pragma unroll
        for (int r = 0; r < MM; ++r) dst[r] = h[r];
    }
}

// ---------------------------------------------------------------------------
// Phase 2: sequential scan h_{c+1} = M_c h_c + v_c over 200 chunks per batch.
// One warp per batch row; lane r owns state component r. M row prefetched
// one chunk ahead via 8x LDG.128; V prefetched too. Explicit 2-chunk
// ping-pong avoids register copies.
// ---------------------------------------------------------------------------
__device__ __forceinline__ void p2_load(float (&m)[32], float& v, size_t bc, int rl)
{
    const float4* row = reinterpret_cast<const float4*>(&g_M[bc * (MM * MMP) + (size_t)rl * MMP]);
    #pragma unroll
    for (int u = 0; u < 8; ++u)
        reinterpret_cast<float4*>(m)[u] = row[u];
    v = g_V[bc * MM + rl];
}

__device__ __forceinline__ float p2_step(const float (&m)[32], float v, float h)
{
    float s0 = v, s1 = 0.f, s2 = 0.f;
    #pragma unroll
    for (int q = 0; q < MM; q += 3) {
        s0 = fmaf(m[q + 0], __shfl_sync(0xffffffffu, h, q + 0), s0);
        s1 = fmaf(m[q + 1], __shfl_sync(0xffffffffu, h, q + 1), s1);
        s2 = fmaf(m[q + 2], __shfl_sync(0xffffffffu, h, q + 2), s2);
    }
    return s0 + (s1 + s2);
}

__global__ __launch_bounds__(32) void k_phase2()
{
    const int b = blockIdx.x;
    const int lane = threadIdx.x;
    const int rl = (lane < MM) ? lane : (MM - 1);
    const size_t b0 = (size_t)b * NN;

    float mA[32], mB[32];
    float vA, vB;
    float h = 0.0f;

    p2_load(mA, vA, b0, rl);            // chunk 0

    for (int c = 0; c < NN; c += 2) {
        // prefetch chunk c+1 (always exists: NN even, c+1 <= 199)
        p2_load(mB, vB, b0 + c + 1, rl);

        if (lane < MM) g_H[(b0 + c) * MM + lane] = h;
        h = p2_step(mA, vA, h);

        // prefetch chunk c+2
        if (c + 2 < NN) p2_load(mA, vA, b0 + c + 2, rl);

        if (lane < MM) g_H[(b0 + c + 1) * MM + lane] = h;
        h = p2_step(mB, vB, h);
    }
}

// ---------------------------------------------------------------------------
// Phase 3: rerun each chunk with the correct initial state, writing outputs.
// One thread per (b, c); coefficients interpolated in registers; fully
// unrolled so the history shift is register renaming.
// ---------------------------------------------------------------------------
__global__ __launch_bounds__(128) void k_phase3(const float* __restrict__ x,
                                                const float* __restrict__ a,
                                                float* __restrict__ out)
{
    const int idx = blockIdx.x * blockDim.x + threadIdx.x;
    if (idx >= BB * NN) return;
    const int b = idx / NN;
    const int c = idx % NN;
    const int cn = (c < NN - 1) ? (c + 1) : c;

    float a0[NA], dd[NA];
    #pragma unroll
    for (int m = 0; m < NA; ++m) {
        const float v0 = a[((size_t)b * NN + c)  * NA + m];
        const float v1 = a[((size_t)b * NN + cn) * NA + m];
        a0[m] = v0;
        dd[m] = (v1 - v0) * (1.0f / (float)PP);
    }

    float h[MM];
    {
        const float* Hp = &g_H[((size_t)b * NN + c) * MM];
        #pragma unroll
        for (int r = 0; r < MM; ++r) h[r] = Hp[r];
    }

    const float4* xp = reinterpret_cast<const float4*>(x + (size_t)b * TT + c * PP);
    float4*       op = reinterpret_cast<float4*>(out + (size_t)b * TT + c * PP);

    #pragma unroll
    for (int u = 0; u < PP / 4; ++u) {
        const float4 xq = xp[u];
        const float xv[4] = { xq.x, xq.y, xq.z, xq.w };
        float yv[4];
        #pragma unroll
        for (int j = 0; j < 4; ++j) {
            const float ft = (float)(u * 4 + j);
            float s0 = 0.f, s1 = 0.f, s2 = 0.f, s3 = 0.f, s4 = 0.f;
            #pragma unroll
            for (int m = 0; m < MM; m += 5) {
                s0 = fmaf(fmaf(ft, dd[m + 1], a0[m + 1]), h[m + 0], s0);
                s1 = fmaf(fmaf(ft, dd[m + 2], a0[m + 2]), h[m + 1], s1);
                s2 = fmaf(fmaf(ft, dd[m + 3], a0[m + 3]), h[m + 2], s2);
                s3 = fmaf(fmaf(ft, dd[m + 4], a0[m + 4]), h[m + 3], s3);
                s4 = fmaf(fmaf(ft, dd[m + 5], a0[m + 5]), h[m + 4], s4);
            }
            const float acc = (s0 + s1) + ((s2 + s3) + s4);
            const float cK = fmaf(ft, dd[0], a0[0]);
            const float y = fmaf(cK, xv[j], -acc);
            #pragma unroll
            for (int m = MM - 1; m > 0; --m) h[m] = h[m - 1];
            h[0] = y;
            yv[j] = y;
        }
        float4 yq;
        yq.x = yv[0]; yq.y = yv[1]; yq.z = yv[2]; yq.w = yv[3];
        op[u] = yq;
    }
}

extern "C" void kernel_launch(void* const* d_in, const int* in_sizes, int n_in,
                              void* d_out, int out_size)
{
    const float* x;
    const float* a;
    if (in_sizes[0] == BB * TT) {
        x = (const float*)d_in[0];
        a = (const float*)d_in[1];
    } else {
        x = (const float*)d_in[1];
        a = (const float*)d_in[0];
    }
    float* out = (float*)d_out;

    dim3 g1(NN, BB);
    k_phase1<<<g1, 32>>>(x, a);
    k_phase2<<<BB, 32>>>();
    const int total = BB * NN;
    k_phase3<<<(total + 127) / 128, 128>>>(x, a, out);
}

// round 12
// speedup vs baseline: 1.8002x; 1.4502x over previous
#include <cuda_runtime.h>
#include <cuda_bf16.h>

// Problem constants
#define BB   64          // batch
#define NN   200         // frames
#define PP   80          // frame period (chunk length)
#define MM   30          // filter order
#define MMP  32          // padded row length for M rows (16B-aligned LDG.128)
#define TT   (NN * PP)   // 16000 samples
#define NA   31          // coeffs per frame (K + 30 taps)
#define H1   20          // phase-1 smem coefficient buffer depth (4 refills)

// Scratch (static __device__, no runtime allocation):
// g_M[bc][r][q] with q padded to 32: M[r][q] = d h_end[r] / d h_start[q]
__device__ float g_M[(size_t)BB * NN * MM * MMP];
__device__ float g_V[(size_t)BB * NN * MM];
__device__ float g_H[(size_t)BB * NN * MM];

// ---------------------------------------------------------------------------
// Phase 1: one warp handles TWO chunks (half-warp each); each lane computes
// TWO unit-response columns (sub 0..14 -> columns 2*sub, 2*sub+1) or the
// driven run (sub 15). Coefficients staged in SMEM rows of 72 floats:
// chunk A at cols [0..31] (taps1..30, K, x), chunk B at cols [36..67]
// (+36 floats = +4 banks -> the dual-address broadcast LDS.128 is
// conflict-free per 64-bit phase). This halves L1 wavefront traffic per
// chunk-step vs one-chunk-per-warp.
// ---------------------------------------------------------------------------
__global__ __launch_bounds__(32, 20) void k_phase1(const float* __restrict__ x,
                                                   const float* __restrict__ a)
{
    const int cpair = blockIdx.x;          // 0..99
    const int b     = blockIdx.y;
    const int lane  = threadIdx.x;
    const int half  = lane >> 4;           // 0 -> chunk A, 1 -> chunk B
    const int sub   = lane & 15;

    const int cA = 2 * cpair;
    const int cB = cA + 1;
    const int c  = half ? cB : cA;

    __shared__ __align__(16) float cs[H1][72];

    // Fill params: lane l (<31) owns coefficient slot l of BOTH chunks.
    // slot m<30 -> tap a_{m+1}; slot 30 -> K (m_src = 0).
    float baseA = 0.f, ddA = 0.f, baseB = 0.f, ddB = 0.f;
    if (lane < 31) {
        const int m_src = (lane < 30) ? (lane + 1) : 0;
        const size_t iA = ((size_t)b * NN + cA) * NA + m_src;
        baseA = a[iA];
        ddA = (a[iA + NA] - baseA) * (1.0f / (float)PP);  // cA+1 == cB, always valid
        const size_t iB = iA + NA;
        baseB = a[iB];
        const float nB = (cB < NN - 1) ? a[iB + NA] : baseB;  // a_pad duplicates last
        ddB = (nB - baseB) * (1.0f / (float)PP);
    }
    const float* xA = x + (size_t)b * TT + (size_t)cA * PP;   // xB = xA + PP

    // Two history register sets (two columns per lane).
    float h0[MM], h1[MM];
    #pragma unroll
    for (int j = 0; j < MM; ++j) {
        h0[j] = (sub < 15 && j == 2 * sub)     ? 1.f : 0.f;
        h1[j] = (sub < 15 && j == 2 * sub + 1) ? 1.f : 0.f;
    }
    const float gsel = (sub == 15) ? 1.f : 0.f;   // driven run: h0=h1=0 init
    const int colbase = half ? 36 : 0;

    for (int r = 0; r < 4; ++r) {
        const int t0 = r * H1;
        __syncwarp();
        if (lane < 31) {
            #pragma unroll
            for (int t = 0; t < H1; ++t) {
                cs[t][lane]      = fmaf((float)(t0 + t), ddA, baseA);
                cs[t][36 + lane] = fmaf((float)(t0 + t), ddB, baseB);
            }
        }
        // x: chunk A slot col 31, chunk B slot col 67
        {
            if (lane < H1)            cs[lane][31]            = xA[t0 + lane];
            else                      cs[lane - H1][67]       = xA[PP + t0 + lane - H1];
            const int tt = lane + 32; // 32..63
            if (tt < 2 * H1)          cs[tt - H1][67]         = xA[PP + t0 + tt - H1];
        }
        __syncwarp();

        #pragma unroll
        for (int t = 0; t < H1; ++t) {
            const float4* row = reinterpret_cast<const float4*>(&cs[t][colbase]);
            float4 q = row[0];
            float A0 = q.x * h0[0],  B0 = q.x * h1[0];
            float A1 = q.y * h0[1],  B1 = q.y * h1[1];
            float A2 = q.z * h0[2],  B2 = q.z * h1[2];
            float A3 = q.w * h0[3],  B3 = q.w * h1[3];
            q = row[1];
            A0 = fmaf(q.x, h0[4],  A0);  B0 = fmaf(q.x, h1[4],  B0);
            A1 = fmaf(q.y, h0[5],  A1);  B1 = fmaf(q.y, h1[5],  B1);
            A2 = fmaf(q.z, h0[6],  A2);  B2 = fmaf(q.z, h1[6],  B2);
            A3 = fmaf(q.w, h0[7],  A3);  B3 = fmaf(q.w, h1[7],  B3);
            q = row[2];
            A0 = fmaf(q.x, h0[8],  A0);  B0 = fmaf(q.x, h1[8],  B0);
            A1 = fmaf(q.y, h0[9],  A1);  B1 = fmaf(q.y, h1[9],  B1);
            A2 = fmaf(q.z, h0[10], A2);  B2 = fmaf(q.z, h1[10], B2);
            A3 = fmaf(q.w, h0[11], A3);  B3 = fmaf(q.w, h1[11], B3);
            q = row[3];
            A0 = fmaf(q.x, h0[12], A0);  B0 = fmaf(q.x, h1[12], B0);
            A1 = fmaf(q.y, h0[13], A1);  B1 = fmaf(q.y, h1[13], B1);
            A2 = fmaf(q.z, h0[14], A2);  B2 = fmaf(q.z, h1[14], B2);
            A3 = fmaf(q.w, h0[15], A3);  B3 = fmaf(q.w, h1[15], B3);
            q = row[4];
            A0 = fmaf(q.x, h0[16], A0);  B0 = fmaf(q.x, h1[16], B0);
            A1 = fmaf(q.y, h0[17], A1);  B1 = fmaf(q.y, h1[17], B1);
            A2 = fmaf(q.z, h0[18], A2);  B2 = fmaf(q.z, h1[18], B2);
            A3 = fmaf(q.w, h0[19], A3);  B3 = fmaf(q.w, h1[19], B3);
            q = row[5];
            A0 = fmaf(q.x, h0[20], A0);  B0 = fmaf(q.x, h1[20], B0);
            A1 = fmaf(q.y, h0[21], A1);  B1 = fmaf(q.y, h1[21], B1);
            A2 = fmaf(q.z, h0[22], A2);  B2 = fmaf(q.z, h1[22], B2);
            A3 = fmaf(q.w, h0[23], A3);  B3 = fmaf(q.w, h1[23], B3);
            q = row[6];
            A0 = fmaf(q.x, h0[24], A0);  B0 = fmaf(q.x, h1[24], B0);
            A1 = fmaf(q.y, h0[25], A1);  B1 = fmaf(q.y, h1[25], B1);
            A2 = fmaf(q.z, h0[26], A2);  B2 = fmaf(q.z, h1[26], B2);
            A3 = fmaf(q.w, h0[27], A3);  B3 = fmaf(q.w, h1[27], B3);
            q = row[7];   // taps 29,30 in .x,.y ; K in .z ; x in .w
            A0 = fmaf(q.x, h0[28], A0);  B0 = fmaf(q.x, h1[28], B0);
            A1 = fmaf(q.y, h0[29], A1);  B1 = fmaf(q.y, h1[29], B1);
            const float accA = (A0 + A1) + (A2 + A3);
            const float accB = (B0 + B1) + (B2 + B3);
            const float y0 = fmaf(gsel * q.w, q.z, -accA);  // driven: +K*x
            const float y1 = -accB;                          // sub15: stays 0

            #pragma unroll
            for (int j = MM - 1; j > 0; --j) { h0[j] = h0[j - 1]; h1[j] = h1[j - 1]; }
            h0[0] = y0; h1[0] = y1;
        }
    }

    const size_t bc = (size_t)b * NN + c;
    if (sub < 15) {
        float* dst = &g_M[bc * (size_t)(MM * MMP)];
        #pragma unroll
        for (int rr = 0; rr < MM; ++rr) {
            float2 p; p.x = h0[rr]; p.y = h1[rr];
            *reinterpret_cast<float2*>(&dst[rr * MMP + 2 * sub]) = p;
        }
    } else {
        float* dst = &g_V[bc * MM];
        #pragma unroll
        for (int rr = 0; rr < MM; ++rr) dst[rr] = h0[rr];
    }
}

// ---------------------------------------------------------------------------
// Phase 2: sequential scan h_{c+1} = M_c h_c + v_c over 200 chunks per batch.
// One warp per batch row; lane r owns state component r. 3-buffer rotation
// with prefetch 3 chunks ahead (covers L2/DRAM latency that 1-ahead missed).
// ---------------------------------------------------------------------------
__device__ __forceinline__ void p2_load(float (&m)[32], float& v, size_t bc, int rl)
{
    const float4* row = reinterpret_cast<const float4*>(&g_M[bc * (MM * MMP) + (size_t)rl * MMP]);
    #pragma unroll
    for (int u = 0; u < 8; ++u)
        reinterpret_cast<float4*>(m)[u] = row[u];
    v = g_V[bc * MM + rl];
}

__device__ __forceinline__ float p2_step(const float (&m)[32], float v, float h)
{
    float s0 = v, s1 = 0.f, s2 = 0.f;
    #pragma unroll
    for (int q = 0; q < MM; q += 3) {
        s0 = fmaf(m[q + 0], __shfl_sync(0xffffffffu, h, q + 0), s0);
        s1 = fmaf(m[q + 1], __shfl_sync(0xffffffffu, h, q + 1), s1);
        s2 = fmaf(m[q + 2], __shfl_sync(0xffffffffu, h, q + 2), s2);
    }
    return s0 + (s1 + s2);
}

__global__ __launch_bounds__(32) void k_phase2()
{
    const int b = blockIdx.x;
    const int lane = threadIdx.x;
    const int rl = (lane < MM) ? lane : (MM - 1);
    const size_t b0 = (size_t)b * NN;

    float m0[32], m1[32], m2[32];
    float v0, v1, v2;
    float h = 0.0f;

    p2_load(m0, v0, b0 + 0, rl);
    p2_load(m1, v1, b0 + 1, rl);
    p2_load(m2, v2, b0 + 2, rl);

    int c = 0;
    for (int it = 0; it < 66; ++it, c += 3) {
        if (lane < MM) g_H[(b0 + c) * MM + lane] = h;
        h = p2_step(m0, v0, h);
        p2_load(m0, v0, b0 + c + 3, rl);                 // c+3 <= 198, always valid

        if (lane < MM) g_H[(b0 + c + 1) * MM + lane] = h;
        h = p2_step(m1, v1, h);
        p2_load(m1, v1, b0 + c + 4, rl);                 // c+4 <= 199, always valid

        if (lane < MM) g_H[(b0 + c + 2) * MM + lane] = h;
        h = p2_step(m2, v2, h);
        if (c + 5 < NN) p2_load(m2, v2, b0 + c + 5, rl);
    }
    // c == 198
    if (lane < MM) g_H[(b0 + 198) * MM + lane] = h;
    h = p2_step(m0, v0, h);
    if (lane < MM) g_H[(b0 + 199) * MM + lane] = h;
}

// ---------------------------------------------------------------------------
// Phase 3: rerun each chunk with the correct initial state, writing outputs.
// One thread per (b, c); coefficients interpolated in registers; fully
// unrolled so the history shift is register renaming.
// ---------------------------------------------------------------------------
__global__ __launch_bounds__(128) void k_phase3(const float* __restrict__ x,
                                                const float* __restrict__ a,
                                                float* __restrict__ out)
{
    const int idx = blockIdx.x * blockDim.x + threadIdx.x;
    if (idx >= BB * NN) return;
    const int b = idx / NN;
    const int c = idx % NN;
    const int cn = (c < NN - 1) ? (c + 1) : c;

    float a0[NA], dd[NA];
    #pragma unroll
    for (int m = 0; m < NA; ++m) {
        const float v0 = a[((size_t)b * NN + c)  * NA + m];
        const float v1 = a[((size_t)b * NN + cn) * NA + m];
        a0[m] = v0;
        dd[m] = (v1 - v0) * (1.0f / (float)PP);
    }

    float h[MM];
    {
        const float* Hp = &g_H[((size_t)b * NN + c) * MM];
        #pragma unroll
        for (int r = 0; r < MM; ++r) h[r] = Hp[r];
    }

    const float4* xp = reinterpret_cast<const float4*>(x + (size_t)b * TT + c * PP);
    float4*       op = reinterpret_cast<float4*>(out + (size_t)b * TT + c * PP);

    #pragma unroll
    for (int u = 0; u < PP / 4; ++u) {
        const float4 xq = xp[u];
        const float xv[4] = { xq.x, xq.y, xq.z, xq.w };
        float yv[4];
        #pragma unroll
        for (int j = 0; j < 4; ++j) {
            const float ft = (float)(u * 4 + j);
            float s0 = 0.f, s1 = 0.f, s2 = 0.f, s3 = 0.f, s4 = 0.f;
            #pragma unroll
            for (int m = 0; m < MM; m += 5) {
                s0 = fmaf(fmaf(ft, dd[m + 1], a0[m + 1]), h[m + 0], s0);
                s1 = fmaf(fmaf(ft, dd[m + 2], a0[m + 2]), h[m + 1], s1);
                s2 = fmaf(fmaf(ft, dd[m + 3], a0[m + 3]), h[m + 2], s2);
                s3 = fmaf(fmaf(ft, dd[m + 4], a0[m + 4]), h[m + 3], s3);
                s4 = fmaf(fmaf(ft, dd[m + 5], a0[m + 5]), h[m + 4], s4);
            }
            const float acc = (s0 + s1) + ((s2 + s3) + s4);
            const float cK = fmaf(ft, dd[0], a0[0]);
            const float y = fmaf(cK, xv[j], -acc);
            #pragma unroll
            for (int m = MM - 1; m > 0; --m) h[m] = h[m - 1];
            h[0] = y;
            yv[j] = y;
        }
        float4 yq;
        yq.x = yv[0]; yq.y = yv[1]; yq.z = yv[2]; yq.w = yv[3];
        op[u] = yq;
    }
}

extern "C" void kernel_launch(void* const* d_in, const int* in_sizes, int n_in,
                              void* d_out, int out_size)
{
    const float* x;
    const float* a;
    if (in_sizes[0] == BB * TT) {
        x = (const float*)d_in[0];
        a = (const float*)d_in[1];
    } else {
        x = (const float*)d_in[1];
        a = (const float*)d_in[0];
    }
    float* out = (float*)d_out;

    dim3 g1(NN / 2, BB);
    k_phase1<<<g1, 32>>>(x, a);
    k_phase2<<<BB, 32>>>();
    const int total = BB * NN;
    k_phase3<<<(total + 127) / 128, 128>>>(x, a, out);
}